// round 4
// baseline (speedup 1.0000x reference)
#include <cuda_runtime.h>
#include <cuda_bf16.h>
#include <math.h>

// Quantized softmax (SoftmaxBernoulli2): rows of 2048 int32 in [-128,127].
// LUT[q] = clip(round(exp((q-255)*is)/es),0,255); idx = x - rowmax + 255 (in [0,255]);
// out = LUT[idx] / sum_row(LUT[idx]) as fp32.
//
// R4: scalar values (no byte packing), REDUX warp reductions (__reduce_max_sync /
// __reduce_add_sync) replacing 5-deep shfl chains, packed 8KB replicated LUT
// (word=(idx>>2)*32+lane, conflict-free; byte via PRMT). Persistent grid-stride
// CTAs with cross-row prefetch.

#define ROW   2048
#define TPB   256
#define VPT   8
#define NWARP (TPB / 32)

__device__ unsigned g_ptab[64];   // 256-entry table packed 4 bytes/word

__global__ void build_table_kernel(const float* __restrict__ input_scale,
                                   const float* __restrict__ exp_scale) {
    int j = threadIdx.x;
    if (j < 64) {
        double is = (double)input_scale[0];
        double es = (double)exp_scale[0];
        unsigned w = 0;
        #pragma unroll
        for (int b = 0; b < 4; b++) {
            int q = 4 * j + b;                      // 0..255 -> quant value q-255
            double r = nearbyint(exp((double)(q - 255) * is) / es);  // half-even
            r = fmin(fmax(r, 0.0), 255.0);
            w |= ((unsigned)(int)r) << (8 * b);
        }
        g_ptab[j] = w;
    }
}

__global__ __launch_bounds__(TPB) void softmax_bernoulli2_kernel(
    const int* __restrict__ x, float* __restrict__ out, int n_rows) {
    __shared__ unsigned s_tab[64 * 32];   // replicated packed LUT, bank == lane
    __shared__ int s_max[NWARP];
    __shared__ int s_sum[NWARP];

    const int tid  = threadIdx.x;
    const int lane = tid & 31;
    const int warp = tid >> 5;

    #pragma unroll
    for (int i = tid; i < 64 * 32; i += TPB) {
        s_tab[i] = g_ptab[i >> 5];
    }
    __syncthreads();

    const long long stride = gridDim.x;
    long long row = blockIdx.x;
    if (row >= n_rows) return;

    // Prefetch first row: thread t owns elements [t*8, t*8+8), two int4.
    int4 a = *(reinterpret_cast<const int4*>(x + row * ROW) + tid * 2);
    int4 b = *(reinterpret_cast<const int4*>(x + row * ROW) + tid * 2 + 1);

    for (; row < n_rows; row += stride) {
        int v[VPT] = {a.x, a.y, a.z, a.w, b.x, b.y, b.z, b.w};

        // Prefetch next row during the reductions.
        long long nrow = row + stride;
        if (nrow < n_rows) {
            const int4* np = reinterpret_cast<const int4*>(x + nrow * ROW) + tid * 2;
            a = np[0];
            b = np[1];
        }

        // ---- block max: scalar local max, single REDUX, inter-warp via smem ----
        int m = v[0];
        #pragma unroll
        for (int k = 1; k < VPT; k++) m = max(m, v[k]);
        m = __reduce_max_sync(0xFFFFFFFFu, m);
        if (lane == 0) s_max[warp] = m;
        __syncthreads();                       // barrier 1
        int xmax = s_max[0];
        #pragma unroll
        for (int w = 1; w < NWARP; w++) xmax = max(xmax, s_max[w]);
        const int c = 255 - xmax;              // idx = v + c in [0,255], no clip needed
        const unsigned laneW = (unsigned)lane;

        // ---- gather from packed LUT + exact int sum ----
        int e[VPT];
        int sum = 0;
        #pragma unroll
        for (int k = 0; k < VPT; k++) {
            unsigned idx = (unsigned)(v[k] + c);
            unsigned w = s_tab[((idx >> 2) << 5) + laneW];
            e[k] = (int)__byte_perm(w, 0, 0x4440u | (idx & 3u));
            sum += e[k];
        }
        sum = (int)__reduce_add_sync(0xFFFFFFFFu, (unsigned)sum);
        if (lane == 0) s_sum[warp] = sum;
        __syncthreads();                       // barrier 2
        int total = s_sum[0];
        #pragma unroll
        for (int w = 1; w < NWARP; w++) total += s_sum[w];

        const float inv = 1.0f / (float)total;

        float4 o0, o1;
        o0.x = (float)e[0] * inv; o0.y = (float)e[1] * inv;
        o0.z = (float)e[2] * inv; o0.w = (float)e[3] * inv;
        o1.x = (float)e[4] * inv; o1.y = (float)e[5] * inv;
        o1.z = (float)e[6] * inv; o1.w = (float)e[7] * inv;
        float4* op = reinterpret_cast<float4*>(out + row * ROW) + tid * 2;
        op[0] = o0;
        op[1] = o1;
    }
}

extern "C" void kernel_launch(void* const* d_in, const int* in_sizes, int n_in,
                              void* d_out, int out_size) {
    const int* x             = (const int*)d_in[0];
    const float* input_scale = (const float*)d_in[1];
    const float* exp_scale   = (const float*)d_in[2];
    float* out = (float*)d_out;

    const int n_rows = in_sizes[0] / ROW;

    int nblocks = 152 * 8;                     // persistent grid; occupancy regs-limited (~6/SM)
    if (nblocks > n_rows) nblocks = n_rows;

    build_table_kernel<<<1, 64>>>(input_scale, exp_scale);
    softmax_bernoulli2_kernel<<<nblocks, TPB>>>(x, out, n_rows);
}

// round 5
// speedup vs baseline: 1.3531x; 1.3531x over previous
#include <cuda_runtime.h>
#include <cuda_bf16.h>
#include <math.h>

// Quantized softmax (SoftmaxBernoulli2): rows of 2048 int32 in [-128,127].
// LUT[q] = clip(round(exp((q-255)*is)/es),0,255); idx = x - rowmax + 255 (in [0,255]);
// out = LUT[idx] / sum_row(LUT[idx]) as fp32.
//
// R5: cp.async double-buffered row staging (prefetch depth 2, zero register cost),
// packed 8KB replicated LUT (conflict-free), scalar shfl reductions (R4 showed REDUX
// regresses), streaming stores. 8 CTAs/SM, persistent grid-stride.

#define ROW   2048
#define TPB   256
#define VPT   8
#define NWARP (TPB / 32)

__device__ unsigned g_ptab[64];   // 256-entry exp table packed 4 bytes/word

__global__ void build_table_kernel(const float* __restrict__ input_scale,
                                   const float* __restrict__ exp_scale) {
    int j = threadIdx.x;
    if (j < 64) {
        double is = (double)input_scale[0];
        double es = (double)exp_scale[0];
        unsigned w = 0;
        #pragma unroll
        for (int b = 0; b < 4; b++) {
            int q = 4 * j + b;                      // 0..255 -> quant value q-255
            double r = nearbyint(exp((double)(q - 255) * is) / es);  // half-even
            r = fmin(fmax(r, 0.0), 255.0);
            w |= ((unsigned)(int)r) << (8 * b);
        }
        g_ptab[j] = w;
    }
}

__device__ __forceinline__ void cp_async16(void* smem, const void* gmem) {
    unsigned saddr = (unsigned)__cvta_generic_to_shared(smem);
    asm volatile("cp.async.cg.shared.global [%0], [%1], 16;\n"
                 :: "r"(saddr), "l"(gmem) : "memory");
}
#define CP_COMMIT() asm volatile("cp.async.commit_group;\n" ::: "memory")
#define CP_WAIT1()  asm volatile("cp.async.wait_group 1;\n" ::: "memory")

__global__ __launch_bounds__(TPB, 8) void softmax_bernoulli2_kernel(
    const int* __restrict__ x, float* __restrict__ out, int n_rows) {
    __shared__ unsigned s_tab[64 * 32];   // replicated packed LUT, bank == lane
    __shared__ int s_buf[2][ROW];         // double-buffered staged rows
    __shared__ int s_max[NWARP];
    __shared__ int s_sum[NWARP];

    const int tid  = threadIdx.x;
    const int lane = tid & 31;
    const int warp = tid >> 5;

    #pragma unroll
    for (int i = tid; i < 64 * 32; i += TPB) {
        s_tab[i] = g_ptab[i >> 5];
    }

    const long long stride = gridDim.x;   // grid is clamped to <= n_rows
    long long row = blockIdx.x;

    // Prime the pipeline: rows row, row+stride into buffers 0,1.
    {
        const int* s0 = x + row * ROW + tid * 4;
        cp_async16(&s_buf[0][tid * 4], s0);
        cp_async16(&s_buf[0][1024 + tid * 4], s0 + 1024);
        CP_COMMIT();
        long long r1 = row + stride;
        if (r1 >= n_rows) r1 = row;       // clamped redundant load, data unused
        const int* s1 = x + r1 * ROW + tid * 4;
        cp_async16(&s_buf[1][tid * 4], s1);
        cp_async16(&s_buf[1][1024 + tid * 4], s1 + 1024);
        CP_COMMIT();
    }

    int p = 0;
    for (; row < n_rows; row += stride, p ^= 1) {
        CP_WAIT1();
        __syncthreads();                  // barrier A: buf[p] ready CTA-wide (also fences LUT fill)

        int4 a = *reinterpret_cast<const int4*>(&s_buf[p][tid * 8]);
        int4 b = *reinterpret_cast<const int4*>(&s_buf[p][tid * 8 + 4]);
        int v[VPT] = {a.x, a.y, a.z, a.w, b.x, b.y, b.z, b.w};

        // ---- block max ----
        int m = v[0];
        #pragma unroll
        for (int k = 1; k < VPT; k++) m = max(m, v[k]);
        #pragma unroll
        for (int o = 16; o > 0; o >>= 1) m = max(m, __shfl_xor_sync(0xFFFFFFFFu, m, o));
        if (lane == 0) s_max[warp] = m;
        __syncthreads();                  // barrier B: max ready AND buf[p] fully consumed

        // Refill buf[p] with row + 2*stride (clamped) — deep prefetch, no regs.
        {
            long long pr = row + 2 * stride;
            if (pr >= n_rows) pr = row;   // redundant but valid address
            const int* sp = x + pr * ROW + tid * 4;
            cp_async16(&s_buf[p][tid * 4], sp);
            cp_async16(&s_buf[p][1024 + tid * 4], sp + 1024);
            CP_COMMIT();
        }

        int xmax = s_max[0];
        #pragma unroll
        for (int w = 1; w < NWARP; w++) xmax = max(xmax, s_max[w]);
        const int c = 255 - xmax;         // idx = v + c in [0,255], no clip needed
        const unsigned laneW = (unsigned)lane;

        // ---- gather from packed LUT + exact int sum ----
        int e[VPT];
        int sum = 0;
        #pragma unroll
        for (int k = 0; k < VPT; k++) {
            unsigned idx = (unsigned)(v[k] + c);
            unsigned w = s_tab[((idx >> 2) << 5) + laneW];
            e[k] = (int)__byte_perm(w, 0, 0x4440u | (idx & 3u));
            sum += e[k];
        }
        #pragma unroll
        for (int o = 16; o > 0; o >>= 1) sum += __shfl_xor_sync(0xFFFFFFFFu, sum, o);
        if (lane == 0) s_sum[warp] = sum;
        __syncthreads();                  // barrier C
        int total = s_sum[0];
        #pragma unroll
        for (int w = 1; w < NWARP; w++) total += s_sum[w];

        const float inv = 1.0f / (float)total;

        float4 o0, o1;
        o0.x = (float)e[0] * inv; o0.y = (float)e[1] * inv;
        o0.z = (float)e[2] * inv; o0.w = (float)e[3] * inv;
        o1.x = (float)e[4] * inv; o1.y = (float)e[5] * inv;
        o1.z = (float)e[6] * inv; o1.w = (float)e[7] * inv;
        float4* op = reinterpret_cast<float4*>(out + row * ROW) + tid * 2;
        __stcs(op, o0);                   // streaming stores: no reuse, spare L2
        __stcs(op + 1, o1);
    }
}

extern "C" void kernel_launch(void* const* d_in, const int* in_sizes, int n_in,
                              void* d_out, int out_size) {
    const int* x             = (const int*)d_in[0];
    const float* input_scale = (const float*)d_in[1];
    const float* exp_scale   = (const float*)d_in[2];
    float* out = (float*)d_out;

    const int n_rows = in_sizes[0] / ROW;

    int nblocks = 152 * 8;                // 8 CTAs/SM (24.7KB smem, 32 regs)
    if (nblocks > n_rows) nblocks = n_rows;

    build_table_kernel<<<1, 64>>>(input_scale, exp_scale);
    softmax_bernoulli2_kernel<<<nblocks, TPB>>>(x, out, n_rows);
}